// round 1
// baseline (speedup 1.0000x reference)
#include <cuda_runtime.h>
#include <math.h>

#define Bq 2
#define Nq 2048
#define Dq 256
#define Hq 8
#define HDq 32
#define DFFq 1024
#define ROWS (Bq*Nq)          // 4096

// ---------------- scratch (device globals; no allocs allowed) ----------------
__device__ float g_qkv[ROWS * 3 * Dq];   // [4096, 768]
__device__ float g_att[ROWS * Dq];       // [4096, 256]
__device__ float g_proj[ROWS * Dq];      // pre-LN (attn proj + bias + x)
__device__ float g_net[ROWS * Dq];       // post-LN (shortcut)
__device__ float g_h1[ROWS * DFFq];      // fc1 out

// ---------------- generic fp32 SGEMM: C = A[MxK] @ B[KxN] (+bias)(+res) -----
// BM=BN=64, BK=16, 256 threads, 4x4 per thread. All dims divide tiles.
__global__ void gemm64(const float* __restrict__ A, const float* __restrict__ B,
                       const float* __restrict__ bias, const float* __restrict__ res,
                       float* __restrict__ C, int M, int N, int K)
{
    __shared__ float As[16][64];
    __shared__ float Bs[16][64];
    const int t  = threadIdx.x;
    const int bm = blockIdx.y * 64;
    const int bn = blockIdx.x * 64;
    const int ty = t >> 4, tx = t & 15;

    const int ar  = t >> 2;          // A row within tile (0..63)
    const int ak  = (t & 3) << 2;    // A k within tile (0,4,8,12)
    const int bkr = t >> 4;          // B k within tile (0..15)
    const int bc  = (t & 15) << 2;   // B col within tile

    float acc[4][4];
    #pragma unroll
    for (int i = 0; i < 4; i++)
        #pragma unroll
        for (int j = 0; j < 4; j++) acc[i][j] = 0.f;

    for (int k0 = 0; k0 < K; k0 += 16) {
        float4 av = *(const float4*)&A[(size_t)(bm + ar) * K + k0 + ak];
        As[ak + 0][ar] = av.x; As[ak + 1][ar] = av.y;
        As[ak + 2][ar] = av.z; As[ak + 3][ar] = av.w;
        *(float4*)&Bs[bkr][bc] = *(const float4*)&B[(size_t)(k0 + bkr) * N + bn + bc];
        __syncthreads();
        #pragma unroll
        for (int k = 0; k < 16; k++) {
            float4 a4 = *(const float4*)&As[k][ty << 2];
            float4 b4 = *(const float4*)&Bs[k][tx << 2];
            float a[4] = {a4.x, a4.y, a4.z, a4.w};
            float b[4] = {b4.x, b4.y, b4.z, b4.w};
            #pragma unroll
            for (int i = 0; i < 4; i++)
                #pragma unroll
                for (int j = 0; j < 4; j++) acc[i][j] = fmaf(a[i], b[j], acc[i][j]);
        }
        __syncthreads();
    }

    #pragma unroll
    for (int i = 0; i < 4; i++) {
        const int row = bm + (ty << 2) + i;
        #pragma unroll
        for (int j = 0; j < 4; j++) {
            const int col = bn + (tx << 2) + j;
            float v = acc[i][j];
            if (bias) v += bias[col];
            if (res)  v += res[(size_t)row * N + col];
            C[(size_t)row * N + col] = v;
        }
    }
}

// ---------------- flash-style fp32 attention ---------------------------------
// grid: (N/QT, B*H), QT=128 threads, 1 thread = 1 query row of one head.
#define QT 128
#define KT 64
__global__ void attn_kernel(const float* __restrict__ qkv, float* __restrict__ out)
{
    __shared__ float ks[KT][HDq];
    __shared__ float vs[KT][HDq];
    __shared__ float ss[QT][KT + 1];   // +1 pad: thread-major access conflict-free

    const int t  = threadIdx.x;
    const int bh = blockIdx.y;
    const int b  = bh >> 3, h = bh & 7;
    const int n  = blockIdx.x * QT + t;
    const float* base = qkv + (size_t)b * Nq * (3 * Dq);
    const float scale = 5.656854249492381f;   // sqrt(32): reference MULTIPLIES

    float q[HDq], O[HDq];
    {
        const float* qp = base + (size_t)n * (3 * Dq) + h * HDq;
        #pragma unroll
        for (int d = 0; d < HDq; d += 4) {
            float4 v = *(const float4*)&qp[d];
            q[d] = v.x; q[d+1] = v.y; q[d+2] = v.z; q[d+3] = v.w;
        }
    }
    #pragma unroll
    for (int d = 0; d < HDq; d++) O[d] = 0.f;
    float m = -1e30f, l = 0.f;

    for (int k0 = 0; k0 < Nq; k0 += KT) {
        // cooperative K/V tile load: 512 float4 per tile, 4 per thread
        #pragma unroll
        for (int i = 0; i < 4; i++) {
            int idx = t + i * QT;       // 0..511
            int r = idx >> 3;           // key row in tile
            int c = (idx & 7) << 2;     // float offset in head dim
            const float* rp = base + (size_t)(k0 + r) * (3 * Dq) + h * HDq + c;
            *(float4*)&ks[r][c] = *(const float4*)(rp + Dq);      // K block
            *(float4*)&vs[r][c] = *(const float4*)(rp + 2 * Dq);  // V block
        }
        __syncthreads();

        float mt = -1e30f;
        #pragma unroll 4
        for (int j = 0; j < KT; j++) {
            float s = 0.f;
            #pragma unroll
            for (int d = 0; d < HDq; d++) s = fmaf(q[d], ks[j][d], s);
            s *= scale;
            ss[t][j] = s;
            mt = fmaxf(mt, s);
        }
        const float m_new = fmaxf(m, mt);
        const float alpha = __expf(m - m_new);
        l *= alpha;
        #pragma unroll
        for (int d = 0; d < HDq; d++) O[d] *= alpha;
        #pragma unroll 2
        for (int j = 0; j < KT; j++) {
            float p = __expf(ss[t][j] - m_new);
            l += p;
            #pragma unroll
            for (int d = 0; d < HDq; d++) O[d] = fmaf(p, vs[j][d], O[d]);
        }
        m = m_new;
        __syncthreads();
    }

    const float inv = 1.f / l;
    float* op = out + ((size_t)(b * Nq + n) * Dq) + h * HDq;
    #pragma unroll
    for (int d = 0; d < HDq; d += 4) {
        float4 v = make_float4(O[d] * inv, O[d+1] * inv, O[d+2] * inv, O[d+3] * inv);
        *(float4*)&op[d] = v;
    }
}

// ---------------- per-row LayerNorm (block=256 threads, 1 elem/thread) -------
__device__ __forceinline__ float blk_sum256(float v, float* sh8)
{
    const int t = threadIdx.x;
    #pragma unroll
    for (int o = 16; o > 0; o >>= 1) v += __shfl_xor_sync(0xffffffffu, v, o);
    if ((t & 31) == 0) sh8[t >> 5] = v;
    __syncthreads();
    float r = 0.f;
    #pragma unroll
    for (int i = 0; i < 8; i++) r += sh8[i];
    __syncthreads();   // allow smem reuse by the next reduction
    return r;
}

__global__ void ln_kernel(const float* __restrict__ in, const float* __restrict__ g,
                          const float* __restrict__ be, float* __restrict__ outp)
{
    __shared__ float sh8[8];
    const int row = blockIdx.x;
    const int t = threadIdx.x;
    const float v = in[(size_t)row * Dq + t];
    const float mu = blk_sum256(v, sh8) * (1.0f / Dq);
    const float d = v - mu;
    const float var = blk_sum256(d * d, sh8) * (1.0f / Dq);
    const float inv = rsqrtf(var + 1e-5f);
    outp[(size_t)row * Dq + t] = d * inv * g[t] + be[t];
}

// ---------------- launch ------------------------------------------------------
extern "C" void kernel_launch(void* const* d_in, const int* in_sizes, int n_in,
                              void* d_out, int out_size)
{
    const float* x      = (const float*)d_in[0];
    const float* qkv_w  = (const float*)d_in[1];
    const float* proj_w = (const float*)d_in[2];
    const float* proj_b = (const float*)d_in[3];
    const float* fc1_w  = (const float*)d_in[4];
    const float* fc1_b  = (const float*)d_in[5];
    const float* fc2_w  = (const float*)d_in[6];
    const float* fc2_b  = (const float*)d_in[7];
    const float* ln1_g  = (const float*)d_in[8];
    const float* ln1_b  = (const float*)d_in[9];
    float* out = (float*)d_out;

    float *p_qkv, *p_att, *p_proj, *p_net, *p_h1;
    cudaGetSymbolAddress((void**)&p_qkv,  g_qkv);
    cudaGetSymbolAddress((void**)&p_att,  g_att);
    cudaGetSymbolAddress((void**)&p_proj, g_proj);
    cudaGetSymbolAddress((void**)&p_net,  g_net);
    cudaGetSymbolAddress((void**)&p_h1,   g_h1);

    // 1) QKV = X @ Wqkv                     [4096,256]@[256,768]
    gemm64<<<dim3(3 * Dq / 64, ROWS / 64), 256>>>(x, qkv_w, nullptr, nullptr,
                                                  p_qkv, ROWS, 3 * Dq, Dq);
    // 2) attention -> [4096,256] (b,n,h*hd layout)
    attn_kernel<<<dim3(Nq / QT, Bq * Hq), QT>>>(p_qkv, p_att);
    // 3) proj + bias + residual x
    gemm64<<<dim3(Dq / 64, ROWS / 64), 256>>>(p_att, proj_w, proj_b, x,
                                              p_proj, ROWS, Dq, Dq);
    // 4) LayerNorm -> shortcut
    ln_kernel<<<ROWS, 256>>>(p_proj, ln1_g, ln1_b, p_net);
    // 5) fc1 + bias                         [4096,256]@[256,1024]
    gemm64<<<dim3(DFFq / 64, ROWS / 64), 256>>>(p_net, fc1_w, fc1_b, nullptr,
                                                p_h1, ROWS, DFFq, Dq);
    // 6) fc2 + bias + shortcut -> d_out     [4096,1024]@[1024,256]
    gemm64<<<dim3(Dq / 64, ROWS / 64), 256>>>(p_h1, fc2_w, fc2_b, p_net,
                                              out, ROWS, Dq, DFFq);
}

// round 2
// speedup vs baseline: 1.0690x; 1.0690x over previous
#include <cuda_runtime.h>
#include <math.h>

#define Bq 2
#define Nq 2048
#define Dq 256
#define Hq 8
#define HDq 32
#define DFFq 1024
#define ROWS (Bq*Nq)          // 4096

// ---------------- scratch (device globals; no allocs allowed) ----------------
__device__ float g_qkv[ROWS * 3 * Dq];   // [4096, 768]
__device__ float g_att[ROWS * Dq];       // [4096, 256]
__device__ float g_proj[ROWS * Dq];      // pre-LN (attn proj + bias + x)
__device__ float g_net[ROWS * Dq];       // post-LN (shortcut)
__device__ float g_h1[ROWS * DFFq];      // fc1 out

// ---------------- double-buffered fp32 SGEMM --------------------------------
// BM=128, BK=16, 256 threads. BN/TN templated: <128,8> or <64,4>.
// C = A[MxK] @ B[KxN] (+bias)(+res)
template<int BN, int TN>
__global__ void __launch_bounds__(256, 2)
gemm_dbuf(const float* __restrict__ A, const float* __restrict__ B,
          const float* __restrict__ bias, const float* __restrict__ res,
          float* __restrict__ C, int M, int N, int K)
{
    constexpr int BM = 128, BK = 16, TM = 8;
    constexpr int AP = BM + 4;            // pad: kills transpose-STS conflicts
    constexpr int BQ = BN / 4;            // float4 per B smem row
    constexpr int NB = (BK * BQ) / 256;   // B float4 loads per thread (2 or 1)

    __shared__ float As[2][BK][AP];
    __shared__ float Bs[2][BK][BN];

    const int t    = threadIdx.x;
    const int bm   = blockIdx.y * BM;
    const int bn   = blockIdx.x * BN;
    const int trow = (t >> 4) * TM;       // 0..120
    const int tcol = (t & 15) * TN;       // 0..BN-TN

    // A tile: 128x16 floats = 512 float4, 2 per thread
    const int a_row0 = (t        ) >> 2, a_kq0 = ((t        ) & 3) << 2;
    const int a_row1 = (t + 256  ) >> 2, a_kq1 = ((t + 256  ) & 3) << 2;

    float4 a_ld[2], b_ld[NB > 0 ? NB : 1];

    float acc[TM][TN];
    #pragma unroll
    for (int i = 0; i < TM; i++)
        #pragma unroll
        for (int j = 0; j < TN; j++) acc[i][j] = 0.f;

    // -- prologue: tile 0 --
    a_ld[0] = *(const float4*)&A[(size_t)(bm + a_row0) * K + a_kq0];
    a_ld[1] = *(const float4*)&A[(size_t)(bm + a_row1) * K + a_kq1];
    #pragma unroll
    for (int i = 0; i < NB; i++) {
        int idx = t + i * 256;
        int kr = idx / BQ, c = (idx % BQ) << 2;
        b_ld[i] = *(const float4*)&B[(size_t)kr * N + bn + c];
    }
    {
        As[0][a_kq0 + 0][a_row0] = a_ld[0].x; As[0][a_kq0 + 1][a_row0] = a_ld[0].y;
        As[0][a_kq0 + 2][a_row0] = a_ld[0].z; As[0][a_kq0 + 3][a_row0] = a_ld[0].w;
        As[0][a_kq1 + 0][a_row1] = a_ld[1].x; As[0][a_kq1 + 1][a_row1] = a_ld[1].y;
        As[0][a_kq1 + 2][a_row1] = a_ld[1].z; As[0][a_kq1 + 3][a_row1] = a_ld[1].w;
        #pragma unroll
        for (int i = 0; i < NB; i++) {
            int idx = t + i * 256;
            int kr = idx / BQ, c = (idx % BQ) << 2;
            *(float4*)&Bs[0][kr][c] = b_ld[i];
        }
    }
    __syncthreads();

    int cur = 0;
    for (int k0 = 0; k0 < K; k0 += BK) {
        const bool more = (k0 + BK) < K;
        if (more) {
            a_ld[0] = *(const float4*)&A[(size_t)(bm + a_row0) * K + k0 + BK + a_kq0];
            a_ld[1] = *(const float4*)&A[(size_t)(bm + a_row1) * K + k0 + BK + a_kq1];
            #pragma unroll
            for (int i = 0; i < NB; i++) {
                int idx = t + i * 256;
                int kr = idx / BQ, c = (idx % BQ) << 2;
                b_ld[i] = *(const float4*)&B[(size_t)(k0 + BK + kr) * N + bn + c];
            }
        }
        #pragma unroll
        for (int k = 0; k < BK; k++) {
            float a[TM], b[TN];
            *(float4*)&a[0] = *(const float4*)&As[cur][k][trow];
            *(float4*)&a[4] = *(const float4*)&As[cur][k][trow + 4];
            #pragma unroll
            for (int j = 0; j < TN; j += 4)
                *(float4*)&b[j] = *(const float4*)&Bs[cur][k][tcol + j];
            #pragma unroll
            for (int i = 0; i < TM; i++)
                #pragma unroll
                for (int j = 0; j < TN; j++)
                    acc[i][j] = fmaf(a[i], b[j], acc[i][j]);
        }
        if (more) {
            const int nxt = cur ^ 1;
            As[nxt][a_kq0 + 0][a_row0] = a_ld[0].x; As[nxt][a_kq0 + 1][a_row0] = a_ld[0].y;
            As[nxt][a_kq0 + 2][a_row0] = a_ld[0].z; As[nxt][a_kq0 + 3][a_row0] = a_ld[0].w;
            As[nxt][a_kq1 + 0][a_row1] = a_ld[1].x; As[nxt][a_kq1 + 1][a_row1] = a_ld[1].y;
            As[nxt][a_kq1 + 2][a_row1] = a_ld[1].z; As[nxt][a_kq1 + 3][a_row1] = a_ld[1].w;
            #pragma unroll
            for (int i = 0; i < NB; i++) {
                int idx = t + i * 256;
                int kr = idx / BQ, c = (idx % BQ) << 2;
                *(float4*)&Bs[nxt][kr][c] = b_ld[i];
            }
            __syncthreads();
            cur = nxt;
        }
    }

    // -- epilogue: bias/residual fused, float4 stores --
    #pragma unroll
    for (int i = 0; i < TM; i++) {
        const int row = bm + trow + i;
        #pragma unroll
        for (int j = 0; j < TN; j += 4) {
            const int col = bn + tcol + j;
            float4 v = make_float4(acc[i][j], acc[i][j + 1], acc[i][j + 2], acc[i][j + 3]);
            if (bias) {
                float4 bb = *(const float4*)&bias[col];
                v.x += bb.x; v.y += bb.y; v.z += bb.z; v.w += bb.w;
            }
            if (res) {
                float4 rr = *(const float4*)&res[(size_t)row * N + col];
                v.x += rr.x; v.y += rr.y; v.z += rr.z; v.w += rr.w;
            }
            *(float4*)&C[(size_t)row * N + col] = v;
        }
    }
}

// ---------------- flash-style fp32 attention ---------------------------------
// grid: (N/QT, B*H), QT=128 threads, 1 thread = 1 query row of one head.
#define QT 128
#define KT 64
__global__ void attn_kernel(const float* __restrict__ qkv, float* __restrict__ out)
{
    __shared__ float ks[KT][HDq];
    __shared__ float vs[KT][HDq];
    __shared__ float ss[QT][KT + 1];   // +1 pad: thread-major access conflict-free

    const int t  = threadIdx.x;
    const int bh = blockIdx.y;
    const int b  = bh >> 3, h = bh & 7;
    const int n  = blockIdx.x * QT + t;
    const float* base = qkv + (size_t)b * Nq * (3 * Dq);
    const float scale = 5.656854249492381f;   // sqrt(32): reference MULTIPLIES

    float q[HDq], O[HDq];
    {
        const float* qp = base + (size_t)n * (3 * Dq) + h * HDq;
        #pragma unroll
        for (int d = 0; d < HDq; d += 4) {
            float4 v = *(const float4*)&qp[d];
            q[d] = v.x; q[d+1] = v.y; q[d+2] = v.z; q[d+3] = v.w;
        }
    }
    #pragma unroll
    for (int d = 0; d < HDq; d++) O[d] = 0.f;
    float m = -1e30f, l = 0.f;

    for (int k0 = 0; k0 < Nq; k0 += KT) {
        // cooperative K/V tile load: 512 float4 per tile, 4 per thread
        #pragma unroll
        for (int i = 0; i < 4; i++) {
            int idx = t + i * QT;       // 0..511
            int r = idx >> 3;           // key row in tile
            int c = (idx & 7) << 2;     // float offset in head dim
            const float* rp = base + (size_t)(k0 + r) * (3 * Dq) + h * HDq + c;
            *(float4*)&ks[r][c] = *(const float4*)(rp + Dq);      // K block
            *(float4*)&vs[r][c] = *(const float4*)(rp + 2 * Dq);  // V block
        }
        __syncthreads();

        float mt = -1e30f;
        #pragma unroll 4
        for (int j = 0; j < KT; j++) {
            float s = 0.f;
            #pragma unroll
            for (int d = 0; d < HDq; d++) s = fmaf(q[d], ks[j][d], s);
            s *= scale;
            ss[t][j] = s;
            mt = fmaxf(mt, s);
        }
        const float m_new = fmaxf(m, mt);
        const float alpha = __expf(m - m_new);
        l *= alpha;
        #pragma unroll
        for (int d = 0; d < HDq; d++) O[d] *= alpha;
        #pragma unroll 2
        for (int j = 0; j < KT; j++) {
            float p = __expf(ss[t][j] - m_new);
            l += p;
            #pragma unroll
            for (int d = 0; d < HDq; d++) O[d] = fmaf(p, vs[j][d], O[d]);
        }
        m = m_new;
        __syncthreads();
    }

    const float inv = 1.f / l;
    float* op = out + ((size_t)(b * Nq + n) * Dq) + h * HDq;
    #pragma unroll
    for (int d = 0; d < HDq; d += 4) {
        float4 v = make_float4(O[d] * inv, O[d+1] * inv, O[d+2] * inv, O[d+3] * inv);
        *(float4*)&op[d] = v;
    }
}

// ---------------- per-row LayerNorm (block=256 threads, 1 elem/thread) -------
__device__ __forceinline__ float blk_sum256(float v, float* sh8)
{
    const int t = threadIdx.x;
    #pragma unroll
    for (int o = 16; o > 0; o >>= 1) v += __shfl_xor_sync(0xffffffffu, v, o);
    if ((t & 31) == 0) sh8[t >> 5] = v;
    __syncthreads();
    float r = 0.f;
    #pragma unroll
    for (int i = 0; i < 8; i++) r += sh8[i];
    __syncthreads();   // allow smem reuse by the next reduction
    return r;
}

__global__ void ln_kernel(const float* __restrict__ in, const float* __restrict__ g,
                          const float* __restrict__ be, float* __restrict__ outp)
{
    __shared__ float sh8[8];
    const int row = blockIdx.x;
    const int t = threadIdx.x;
    const float v = in[(size_t)row * Dq + t];
    const float mu = blk_sum256(v, sh8) * (1.0f / Dq);
    const float d = v - mu;
    const float var = blk_sum256(d * d, sh8) * (1.0f / Dq);
    const float inv = rsqrtf(var + 1e-5f);
    outp[(size_t)row * Dq + t] = d * inv * g[t] + be[t];
}

// ---------------- launch ------------------------------------------------------
extern "C" void kernel_launch(void* const* d_in, const int* in_sizes, int n_in,
                              void* d_out, int out_size)
{
    const float* x      = (const float*)d_in[0];
    const float* qkv_w  = (const float*)d_in[1];
    const float* proj_w = (const float*)d_in[2];
    const float* proj_b = (const float*)d_in[3];
    const float* fc1_w  = (const float*)d_in[4];
    const float* fc1_b  = (const float*)d_in[5];
    const float* fc2_w  = (const float*)d_in[6];
    const float* fc2_b  = (const float*)d_in[7];
    const float* ln1_g  = (const float*)d_in[8];
    const float* ln1_b  = (const float*)d_in[9];
    float* out = (float*)d_out;

    float *p_qkv, *p_att, *p_proj, *p_net, *p_h1;
    cudaGetSymbolAddress((void**)&p_qkv,  g_qkv);
    cudaGetSymbolAddress((void**)&p_att,  g_att);
    cudaGetSymbolAddress((void**)&p_proj, g_proj);
    cudaGetSymbolAddress((void**)&p_net,  g_net);
    cudaGetSymbolAddress((void**)&p_h1,   g_h1);

    // 1) QKV = X @ Wqkv                     [4096,256]@[256,768]
    gemm_dbuf<128, 8><<<dim3(3 * Dq / 128, ROWS / 128), 256>>>(
        x, qkv_w, nullptr, nullptr, p_qkv, ROWS, 3 * Dq, Dq);
    // 2) attention -> [4096,256] (b,n,h*hd layout)
    attn_kernel<<<dim3(Nq / QT, Bq * Hq), QT>>>(p_qkv, p_att);
    // 3) proj + bias + residual x           [4096,256]@[256,256]
    gemm_dbuf<64, 4><<<dim3(Dq / 64, ROWS / 128), 256>>>(
        p_att, proj_w, proj_b, x, p_proj, ROWS, Dq, Dq);
    // 4) LayerNorm -> shortcut
    ln_kernel<<<ROWS, 256>>>(p_proj, ln1_g, ln1_b, p_net);
    // 5) fc1 + bias                         [4096,256]@[256,1024]
    gemm_dbuf<128, 8><<<dim3(DFFq / 128, ROWS / 128), 256>>>(
        p_net, fc1_w, fc1_b, nullptr, p_h1, ROWS, DFFq, Dq);
    // 6) fc2 + bias + shortcut -> d_out     [4096,1024]@[1024,256]
    gemm_dbuf<64, 4><<<dim3(Dq / 64, ROWS / 128), 256>>>(
        p_h1, fc2_w, fc2_b, p_net, out, ROWS, Dq, DFFq);
}

// round 4
// speedup vs baseline: 1.1956x; 1.1185x over previous
#include <cuda_runtime.h>
#include <cuda_bf16.h>
#include <math.h>
#include <stdint.h>

#define Bq 2
#define Nq 2048
#define Dq 256
#define Hq 8
#define HDq 32
#define DFFq 1024
#define ROWS (Bq*Nq)          // 4096

// ---------------- scratch (device globals; no allocs allowed) ----------------
__device__ float g_qkv[ROWS * 3 * Dq];   // [4096, 768]
__device__ float g_att[ROWS * Dq];       // [4096, 256]
__device__ float g_proj[ROWS * Dq];      // pre-LN (attn proj + bias + x)
__device__ float g_net[ROWS * Dq];       // post-LN (shortcut)
__device__ float g_h1[ROWS * DFFq];      // fc1 out

// ---------------- helpers ------------------------------------------------------
__device__ __forceinline__ uint32_t smem_u32(const void* p) {
    uint32_t a;
    asm("{ .reg .u64 t; cvta.to.shared.u64 t, %1; cvt.u32.u64 %0, t; }"
        : "=r"(a) : "l"(p));
    return a;
}

// fp32x4 -> packed hi-bf16x2 pairs + lo-bf16x2 pairs (two-term split)
__device__ __forceinline__ void split4(float4 a, uint32_t& h01, uint32_t& h23,
                                       uint32_t& g01, uint32_t& g23) {
    asm("cvt.rn.bf16x2.f32 %0, %1, %2;" : "=r"(h01) : "f"(a.y), "f"(a.x));
    asm("cvt.rn.bf16x2.f32 %0, %1, %2;" : "=r"(h23) : "f"(a.w), "f"(a.z));
    float l0 = a.x - __int_as_float(h01 << 16);
    float l1 = a.y - __int_as_float(h01 & 0xffff0000u);
    float l2 = a.z - __int_as_float(h23 << 16);
    float l3 = a.w - __int_as_float(h23 & 0xffff0000u);
    asm("cvt.rn.bf16x2.f32 %0, %1, %2;" : "=r"(g01) : "f"(l1), "f"(l0));
    asm("cvt.rn.bf16x2.f32 %0, %1, %2;" : "=r"(g23) : "f"(l3), "f"(l2));
}

#define LDSM4(r, addr) \
    asm volatile("ldmatrix.sync.aligned.m8n8.x4.shared.b16 {%0,%1,%2,%3}, [%4];" \
        : "=r"((r)[0]), "=r"((r)[1]), "=r"((r)[2]), "=r"((r)[3]) : "r"(addr))

#define MMA16816(d, a, b0, b1) \
    asm volatile("mma.sync.aligned.m16n8k16.row.col.f32.bf16.bf16.f32 " \
        "{%0,%1,%2,%3}, {%4,%5,%6,%7}, {%8,%9}, {%0,%1,%2,%3};" \
        : "+f"((d)[0]), "+f"((d)[1]), "+f"((d)[2]), "+f"((d)[3]) \
        : "r"((a)[0]), "r"((a)[1]), "r"((a)[2]), "r"((a)[3]), "r"(b0), "r"(b1))

// ================= bf16x3-split tensor-core GEMM (mma.sync) ==================
// C[M,N] = A[M,K]@B[K,N] (+bias)(+res). CTA tile 128x64, BK=32, 256 threads.
// Smem rows: [hi bf16 x32 | lo bf16 x32 | pad] = 144 bytes (conflict-free LDSM).
#define ASTRIDE 144
__global__ void __launch_bounds__(256)
gemm_mma(const float* __restrict__ A, const float* __restrict__ B,
         const float* __restrict__ bias, const float* __restrict__ res,
         float* __restrict__ C, int M, int N, int K)
{
    __shared__ __align__(16) char As[128 * ASTRIDE];   // A: 128 rows
    __shared__ __align__(16) char Bs[64 * ASTRIDE];    // B^T: 64 n-rows

    const int t    = threadIdx.x;
    const int wid  = t >> 5, lane = t & 31;
    const int bm   = blockIdx.y * 128;
    const int bn   = blockIdx.x * 64;
    const int wm   = (wid & 3) * 32;     // warp m offset in tile
    const int wn   = (wid >> 2) * 32;    // warp n offset in tile

    const uint32_t aBase = smem_u32(As);
    const uint32_t bBase = smem_u32(Bs);

    float acc[2][4][4];
    #pragma unroll
    for (int i = 0; i < 2; i++)
        #pragma unroll
        for (int j = 0; j < 4; j++)
            #pragma unroll
            for (int k = 0; k < 4; k++) acc[i][j][k] = 0.f;

    // ldmatrix per-lane address pieces
    const uint32_t a_row = wm + (lane & 15);
    const uint32_t a_off = (lane >> 4) << 4;                       // 0 / 16 B
    const uint32_t b_row = wn + (lane & 7) + ((lane >> 4) << 3);
    const uint32_t b_off = ((lane >> 3) & 1) << 4;

    for (int k0 = 0; k0 < K; k0 += 32) {
        // ---- A tile: 128x32 fp32 -> hi/lo bf16 -----------------------------
        #pragma unroll
        for (int i = 0; i < 4; i++) {
            int idx = i * 256 + t;
            int r = idx >> 3, q = (idx & 7) << 2;      // q: k elem 0,4..28
            float4 a = *(const float4*)&A[(size_t)(bm + r) * K + k0 + q];
            uint32_t h01, h23, g01, g23;
            split4(a, h01, h23, g01, g23);
            uint32_t ad = aBase + r * ASTRIDE + (q << 1);
            asm volatile("st.shared.v2.b32 [%0], {%1,%2};" :: "r"(ad), "r"(h01), "r"(h23));
            asm volatile("st.shared.v2.b32 [%0], {%1,%2};" :: "r"(ad + 64), "r"(g01), "r"(g23));
        }
        // ---- B tile: 32x64 fp32 -> transposed [n][k] hi/lo bf16 ------------
        #pragma unroll
        for (int i = 0; i < 2; i++) {
            int idx = i * 256 + t;
            int n = idx & 63, kg = idx >> 6;           // kg 0..7
            int k = kg << 2;
            const float* bp = &B[(size_t)(k0 + k) * N + bn + n];
            float4 v = make_float4(bp[0], bp[N], bp[2 * (size_t)N], bp[3 * (size_t)N]);
            uint32_t h01, h23, g01, g23;
            split4(v, h01, h23, g01, g23);
            uint32_t bd = bBase + n * ASTRIDE + (k << 1);
            asm volatile("st.shared.v2.b32 [%0], {%1,%2};" :: "r"(bd), "r"(h01), "r"(h23));
            asm volatile("st.shared.v2.b32 [%0], {%1,%2};" :: "r"(bd + 64), "r"(g01), "r"(g23));
        }
        __syncthreads();

        // ---- compute: 2 k16-steps, 3-term split MMAs ------------------------
        #pragma unroll
        for (int ks = 0; ks < 2; ks++) {
            uint32_t ah[2][4], al[2][4], bh[2][4], bl[2][4];
            #pragma unroll
            for (int mt = 0; mt < 2; mt++) {
                uint32_t ad = aBase + (a_row + mt * 16) * ASTRIDE + (ks << 5) + a_off;
                LDSM4(ah[mt], ad);
                LDSM4(al[mt], ad + 64);
            }
            #pragma unroll
            for (int gg = 0; gg < 2; gg++) {
                uint32_t bd = bBase + (b_row + gg * 16) * ASTRIDE + (ks << 5) + b_off;
                LDSM4(bh[gg], bd);
                LDSM4(bl[gg], bd + 64);
            }
            #pragma unroll
            for (int mt = 0; mt < 2; mt++)
                #pragma unroll
                for (int nt = 0; nt < 4; nt++) {
                    const int gsel = nt >> 1, rsel = (nt & 1) << 1;
                    uint32_t bh0 = bh[gsel][rsel], bh1 = bh[gsel][rsel + 1];
                    uint32_t bl0 = bl[gsel][rsel], bl1 = bl[gsel][rsel + 1];
                    MMA16816(acc[mt][nt], ah[mt], bh0, bh1);
                    MMA16816(acc[mt][nt], ah[mt], bl0, bl1);
                    MMA16816(acc[mt][nt], al[mt], bh0, bh1);
                }
        }
        __syncthreads();
    }

    // ---- epilogue: fragment layout d0,d1 -> (row, col..col+1); d2,d3 -> row+8
    const int gr = lane >> 2, c2 = (lane & 3) << 1;
    #pragma unroll
    for (int mt = 0; mt < 2; mt++)
        #pragma unroll
        for (int nt = 0; nt < 4; nt++) {
            const int row = bm + wm + mt * 16 + gr;
            const int col = bn + wn + nt * 8 + c2;
            float2 v0 = make_float2(acc[mt][nt][0], acc[mt][nt][1]);
            float2 v1 = make_float2(acc[mt][nt][2], acc[mt][nt][3]);
            if (bias) {
                float2 bb = *(const float2*)&bias[col];
                v0.x += bb.x; v0.y += bb.y; v1.x += bb.x; v1.y += bb.y;
            }
            if (res) {
                float2 r0 = *(const float2*)&res[(size_t)row * N + col];
                float2 r1 = *(const float2*)&res[(size_t)(row + 8) * N + col];
                v0.x += r0.x; v0.y += r0.y; v1.x += r1.x; v1.y += r1.y;
            }
            *(float2*)&C[(size_t)row * N + col] = v0;
            *(float2*)&C[(size_t)(row + 8) * N + col] = v1;
        }
}

// ---------------- flash-style fp32 attention ---------------------------------
#define QT 128
#define KT 64
__global__ void attn_kernel(const float* __restrict__ qkv, float* __restrict__ out)
{
    __shared__ float ks[KT][HDq];
    __shared__ float vs[KT][HDq];
    __shared__ float ss[QT][KT + 1];

    const int t  = threadIdx.x;
    const int bh = blockIdx.y;
    const int b  = bh >> 3, h = bh & 7;
    const int n  = blockIdx.x * QT + t;
    const float* base = qkv + (size_t)b * Nq * (3 * Dq);
    const float scale = 5.656854249492381f;   // sqrt(32): reference MULTIPLIES

    float q[HDq], O[HDq];
    {
        const float* qp = base + (size_t)n * (3 * Dq) + h * HDq;
        #pragma unroll
        for (int d = 0; d < HDq; d += 4) {
            float4 v = *(const float4*)&qp[d];
            q[d] = v.x; q[d+1] = v.y; q[d+2] = v.z; q[d+3] = v.w;
        }
    }
    #pragma unroll
    for (int d = 0; d < HDq; d++) O[d] = 0.f;
    float m = -1e30f, l = 0.f;

    for (int k0 = 0; k0 < Nq; k0 += KT) {
        #pragma unroll
        for (int i = 0; i < 4; i++) {
            int idx = t + i * QT;
            int r = idx >> 3;
            int c = (idx & 7) << 2;
            const float* rp = base + (size_t)(k0 + r) * (3 * Dq) + h * HDq + c;
            *(float4*)&ks[r][c] = *(const float4*)(rp + Dq);
            *(float4*)&vs[r][c] = *(const float4*)(rp + 2 * Dq);
        }
        __syncthreads();

        float mt = -1e30f;
        #pragma unroll 4
        for (int j = 0; j < KT; j++) {
            float s = 0.f;
            #pragma unroll
            for (int d = 0; d < HDq; d++) s = fmaf(q[d], ks[j][d], s);
            s *= scale;
            ss[t][j] = s;
            mt = fmaxf(mt, s);
        }
        const float m_new = fmaxf(m, mt);
        const float alpha = __expf(m - m_new);
        l *= alpha;
        #pragma unroll
        for (int d = 0; d < HDq; d++) O[d] *= alpha;
        #pragma unroll 2
        for (int j = 0; j < KT; j++) {
            float p = __expf(ss[t][j] - m_new);
            l += p;
            #pragma unroll
            for (int d = 0; d < HDq; d++) O[d] = fmaf(p, vs[j][d], O[d]);
        }
        m = m_new;
        __syncthreads();
    }

    const float inv = 1.f / l;
    float* op = out + ((size_t)(b * Nq + n) * Dq) + h * HDq;
    #pragma unroll
    for (int d = 0; d < HDq; d += 4) {
        float4 v = make_float4(O[d] * inv, O[d+1] * inv, O[d+2] * inv, O[d+3] * inv);
        *(float4*)&op[d] = v;
    }
}

// ---------------- per-row LayerNorm -------------------------------------------
__device__ __forceinline__ float blk_sum256(float v, float* sh8)
{
    const int t = threadIdx.x;
    #pragma unroll
    for (int o = 16; o > 0; o >>= 1) v += __shfl_xor_sync(0xffffffffu, v, o);
    if ((t & 31) == 0) sh8[t >> 5] = v;
    __syncthreads();
    float r = 0.f;
    #pragma unroll
    for (int i = 0; i < 8; i++) r += sh8[i];
    __syncthreads();
    return r;
}

__global__ void ln_kernel(const float* __restrict__ in, const float* __restrict__ g,
                          const float* __restrict__ be, float* __restrict__ outp)
{
    __shared__ float sh8[8];
    const int row = blockIdx.x;
    const int t = threadIdx.x;
    const float v = in[(size_t)row * Dq + t];
    const float mu = blk_sum256(v, sh8) * (1.0f / Dq);
    const float d = v - mu;
    const float var = blk_sum256(d * d, sh8) * (1.0f / Dq);
    const float inv = rsqrtf(var + 1e-5f);
    outp[(size_t)row * Dq + t] = d * inv * g[t] + be[t];
}

// ---------------- launch ------------------------------------------------------
extern "C" void kernel_launch(void* const* d_in, const int* in_sizes, int n_in,
                              void* d_out, int out_size)
{
    const float* x      = (const float*)d_in[0];
    const float* qkv_w  = (const float*)d_in[1];
    const float* proj_w = (const float*)d_in[2];
    const float* proj_b = (const float*)d_in[3];
    const float* fc1_w  = (const float*)d_in[4];
    const float* fc1_b  = (const float*)d_in[5];
    const float* fc2_w  = (const float*)d_in[6];
    const float* fc2_b  = (const float*)d_in[7];
    const float* ln1_g  = (const float*)d_in[8];
    const float* ln1_b  = (const float*)d_in[9];
    float* out = (float*)d_out;

    float *p_qkv, *p_att, *p_proj, *p_net, *p_h1;
    cudaGetSymbolAddress((void**)&p_qkv,  g_qkv);
    cudaGetSymbolAddress((void**)&p_att,  g_att);
    cudaGetSymbolAddress((void**)&p_proj, g_proj);
    cudaGetSymbolAddress((void**)&p_net,  g_net);
    cudaGetSymbolAddress((void**)&p_h1,   g_h1);

    // 1) QKV = X @ Wqkv                     [4096,256]@[256,768]
    gemm_mma<<<dim3(3 * Dq / 64, ROWS / 128), 256>>>(
        x, qkv_w, nullptr, nullptr, p_qkv, ROWS, 3 * Dq, Dq);
    // 2) attention -> [4096,256]
    attn_kernel<<<dim3(Nq / QT, Bq * Hq), QT>>>(p_qkv, p_att);
    // 3) proj + bias + residual x           [4096,256]@[256,256]
    gemm_mma<<<dim3(Dq / 64, ROWS / 128), 256>>>(
        p_att, proj_w, proj_b, x, p_proj, ROWS, Dq, Dq);
    // 4) LayerNorm -> shortcut
    ln_kernel<<<ROWS, 256>>>(p_proj, ln1_g, ln1_b, p_net);
    // 5) fc1 + bias                         [4096,256]@[256,1024]
    gemm_mma<<<dim3(DFFq / 64, ROWS / 128), 256>>>(
        p_net, fc1_w, fc1_b, nullptr, p_h1, ROWS, DFFq, Dq);
    // 6) fc2 + bias + shortcut -> d_out     [4096,1024]@[1024,256]
    gemm_mma<<<dim3(Dq / 64, ROWS / 128), 256>>>(
        p_h1, fc2_w, fc2_b, p_net, out, ROWS, Dq, DFFq);
}

// round 5
// speedup vs baseline: 2.8766x; 2.4060x over previous
#include <cuda_runtime.h>
#include <cuda_bf16.h>
#include <math.h>
#include <stdint.h>

#define Bq 2
#define Nq 2048
#define Dq 256
#define Hq 8
#define HDq 32
#define DFFq 1024
#define ROWS (Bq*Nq)          // 4096

// ---------------- scratch (device globals; no allocs allowed) ----------------
__device__ float g_qkv[ROWS * 3 * Dq];   // [4096, 768]
__device__ float g_att[ROWS * Dq];       // [4096, 256]
__device__ float g_proj[ROWS * Dq];      // pre-LN (attn proj + bias + x)
__device__ float g_net[ROWS * Dq];       // post-LN (shortcut)
__device__ float g_h1[ROWS * DFFq];      // fc1 out

// ---------------- helpers ------------------------------------------------------
__device__ __forceinline__ uint32_t smem_u32(const void* p) {
    uint32_t a;
    asm("{ .reg .u64 t; cvta.to.shared.u64 t, %1; cvt.u32.u64 %0, t; }"
        : "=r"(a) : "l"(p));
    return a;
}

// fp32x4 -> packed hi-bf16x2 pairs + lo-bf16x2 pairs (two-term split)
__device__ __forceinline__ void split4(float4 a, uint32_t& h01, uint32_t& h23,
                                       uint32_t& g01, uint32_t& g23) {
    asm("cvt.rn.bf16x2.f32 %0, %1, %2;" : "=r"(h01) : "f"(a.y), "f"(a.x));
    asm("cvt.rn.bf16x2.f32 %0, %1, %2;" : "=r"(h23) : "f"(a.w), "f"(a.z));
    float l0 = a.x - __int_as_float(h01 << 16);
    float l1 = a.y - __int_as_float(h01 & 0xffff0000u);
    float l2 = a.z - __int_as_float(h23 << 16);
    float l3 = a.w - __int_as_float(h23 & 0xffff0000u);
    asm("cvt.rn.bf16x2.f32 %0, %1, %2;" : "=r"(g01) : "f"(l1), "f"(l0));
    asm("cvt.rn.bf16x2.f32 %0, %1, %2;" : "=r"(g23) : "f"(l3), "f"(l2));
}
// pack (hi=b, lo=a) + bf16 residual pack
__device__ __forceinline__ void split2(float a, float b, uint32_t& h, uint32_t& g) {
    asm("cvt.rn.bf16x2.f32 %0, %1, %2;" : "=r"(h) : "f"(b), "f"(a));
    float la = a - __int_as_float(h << 16);
    float lb = b - __int_as_float(h & 0xffff0000u);
    asm("cvt.rn.bf16x2.f32 %0, %1, %2;" : "=r"(g) : "f"(lb), "f"(la));
}

#define LDSM4(r, addr) \
    asm volatile("ldmatrix.sync.aligned.m8n8.x4.shared.b16 {%0,%1,%2,%3}, [%4];" \
        : "=r"((r)[0]), "=r"((r)[1]), "=r"((r)[2]), "=r"((r)[3]) : "r"(addr))

#define LDSM4_T(r, addr) \
    asm volatile("ldmatrix.sync.aligned.m8n8.x4.trans.shared.b16 {%0,%1,%2,%3}, [%4];" \
        : "=r"((r)[0]), "=r"((r)[1]), "=r"((r)[2]), "=r"((r)[3]) : "r"(addr))

#define MMA16816(d, a, b0, b1) \
    asm volatile("mma.sync.aligned.m16n8k16.row.col.f32.bf16.bf16.f32 " \
        "{%0,%1,%2,%3}, {%4,%5,%6,%7}, {%8,%9}, {%0,%1,%2,%3};" \
        : "+f"((d)[0]), "+f"((d)[1]), "+f"((d)[2]), "+f"((d)[3]) \
        : "r"((a)[0]), "r"((a)[1]), "r"((a)[2]), "r"((a)[3]), "r"(b0), "r"(b1))

#define ASTRIDE 144

// ================= bf16x3-split tensor-core GEMM (mma.sync) ==================
// C[M,N] = A[M,K]@B[K,N] (+bias)(+res). CTA tile 128x64, BK=32, 256 threads.
__global__ void __launch_bounds__(256)
gemm_mma(const float* __restrict__ A, const float* __restrict__ B,
         const float* __restrict__ bias, const float* __restrict__ res,
         float* __restrict__ C, int M, int N, int K)
{
    __shared__ __align__(16) char As[128 * ASTRIDE];
    __shared__ __align__(16) char Bs[64 * ASTRIDE];

    const int t    = threadIdx.x;
    const int wid  = t >> 5, lane = t & 31;
    const int bm   = blockIdx.y * 128;
    const int bn   = blockIdx.x * 64;
    const int wm   = (wid & 3) * 32;
    const int wn   = (wid >> 2) * 32;

    const uint32_t aBase = smem_u32(As);
    const uint32_t bBase = smem_u32(Bs);

    float acc[2][4][4];
    #pragma unroll
    for (int i = 0; i < 2; i++)
        #pragma unroll
        for (int j = 0; j < 4; j++)
            #pragma unroll
            for (int k = 0; k < 4; k++) acc[i][j][k] = 0.f;

    const uint32_t a_row = wm + (lane & 15);
    const uint32_t a_off = (lane >> 4) << 4;
    const uint32_t b_row = wn + (lane & 7) + ((lane >> 4) << 3);
    const uint32_t b_off = ((lane >> 3) & 1) << 4;

    for (int k0 = 0; k0 < K; k0 += 32) {
        #pragma unroll
        for (int i = 0; i < 4; i++) {
            int idx = i * 256 + t;
            int r = idx >> 3, q = (idx & 7) << 2;
            float4 a = *(const float4*)&A[(size_t)(bm + r) * K + k0 + q];
            uint32_t h01, h23, g01, g23;
            split4(a, h01, h23, g01, g23);
            uint32_t ad = aBase + r * ASTRIDE + (q << 1);
            asm volatile("st.shared.v2.b32 [%0], {%1,%2};" :: "r"(ad), "r"(h01), "r"(h23));
            asm volatile("st.shared.v2.b32 [%0], {%1,%2};" :: "r"(ad + 64), "r"(g01), "r"(g23));
        }
        #pragma unroll
        for (int i = 0; i < 2; i++) {
            int idx = i * 256 + t;
            int n = idx & 63, kg = idx >> 6;
            int k = kg << 2;
            const float* bp = &B[(size_t)(k0 + k) * N + bn + n];
            float4 v = make_float4(bp[0], bp[N], bp[2 * (size_t)N], bp[3 * (size_t)N]);
            uint32_t h01, h23, g01, g23;
            split4(v, h01, h23, g01, g23);
            uint32_t bd = bBase + n * ASTRIDE + (k << 1);
            asm volatile("st.shared.v2.b32 [%0], {%1,%2};" :: "r"(bd), "r"(h01), "r"(h23));
            asm volatile("st.shared.v2.b32 [%0], {%1,%2};" :: "r"(bd + 64), "r"(g01), "r"(g23));
        }
        __syncthreads();

        #pragma unroll
        for (int ks = 0; ks < 2; ks++) {
            uint32_t ah[2][4], al[2][4], bh[2][4], bl[2][4];
            #pragma unroll
            for (int mt = 0; mt < 2; mt++) {
                uint32_t ad = aBase + (a_row + mt * 16) * ASTRIDE + (ks << 5) + a_off;
                LDSM4(ah[mt], ad);
                LDSM4(al[mt], ad + 64);
            }
            #pragma unroll
            for (int gg = 0; gg < 2; gg++) {
                uint32_t bd = bBase + (b_row + gg * 16) * ASTRIDE + (ks << 5) + b_off;
                LDSM4(bh[gg], bd);
                LDSM4(bl[gg], bd + 64);
            }
            #pragma unroll
            for (int mt = 0; mt < 2; mt++)
                #pragma unroll
                for (int nt = 0; nt < 4; nt++) {
                    const int gsel = nt >> 1, rsel = (nt & 1) << 1;
                    uint32_t bh0 = bh[gsel][rsel], bh1 = bh[gsel][rsel + 1];
                    uint32_t bl0 = bl[gsel][rsel], bl1 = bl[gsel][rsel + 1];
                    MMA16816(acc[mt][nt], ah[mt], bh0, bh1);
                    MMA16816(acc[mt][nt], ah[mt], bl0, bl1);
                    MMA16816(acc[mt][nt], al[mt], bh0, bh1);
                }
        }
        __syncthreads();
    }

    const int gr = lane >> 2, c2 = (lane & 3) << 1;
    #pragma unroll
    for (int mt = 0; mt < 2; mt++)
        #pragma unroll
        for (int nt = 0; nt < 4; nt++) {
            const int row = bm + wm + mt * 16 + gr;
            const int col = bn + wn + nt * 8 + c2;
            float2 v0 = make_float2(acc[mt][nt][0], acc[mt][nt][1]);
            float2 v1 = make_float2(acc[mt][nt][2], acc[mt][nt][3]);
            if (bias) {
                float2 bb = *(const float2*)&bias[col];
                v0.x += bb.x; v0.y += bb.y; v1.x += bb.x; v1.y += bb.y;
            }
            if (res) {
                float2 r0 = *(const float2*)&res[(size_t)row * N + col];
                float2 r1 = *(const float2*)&res[(size_t)(row + 8) * N + col];
                v0.x += r0.x; v0.y += r0.y; v1.x += r1.x; v1.y += r1.y;
            }
            *(float2*)&C[(size_t)row * N + col] = v0;
            *(float2*)&C[(size_t)(row + 8) * N + col] = v1;
        }
}

// ================= tensor-core flash attention (mma.sync, bf16x3 split) ======
// grid (Nq/128, B*H), 256 threads = 8 warps x m16. KV tiles of 64 keys.
#define SCALE_ATT 5.656854249492381f
__global__ void __launch_bounds__(256)
attn_mma(const float* __restrict__ qkv, float* __restrict__ out)
{
    __shared__ __align__(16) char Qs[128 * ASTRIDE];
    __shared__ __align__(16) char Ks[64 * ASTRIDE];
    __shared__ __align__(16) char Vs[64 * ASTRIDE];

    const int t = threadIdx.x, wid = t >> 5, lane = t & 31;
    const int q0 = blockIdx.x * 128;
    const int bh = blockIdx.y;
    const int b = bh >> 3, h = bh & 7;
    const float* base = qkv + (size_t)b * Nq * 768 + h * HDq;

    const uint32_t qB = smem_u32(Qs), kB = smem_u32(Ks), vB = smem_u32(Vs);

    // ---- Q tile once: 128 x 32 fp32 -> hi/lo bf16 ----------------------------
    #pragma unroll
    for (int i = 0; i < 4; i++) {
        int idx = i * 256 + t;
        int r = idx >> 3, q = (idx & 7) << 2;
        float4 a = *(const float4*)&base[(size_t)(q0 + r) * 768 + q];
        uint32_t h01, h23, g01, g23;
        split4(a, h01, h23, g01, g23);
        uint32_t ad = qB + r * ASTRIDE + (q << 1);
        asm volatile("st.shared.v2.b32 [%0], {%1,%2};" :: "r"(ad), "r"(h01), "r"(h23));
        asm volatile("st.shared.v2.b32 [%0], {%1,%2};" :: "r"(ad + 64), "r"(g01), "r"(g23));
    }

    const int wm16 = wid * 16;
    const uint32_t a_row = wm16 + (lane & 15);
    const uint32_t a_off = (lane >> 4) << 4;
    const uint32_t kb_part = (lane & 7) + ((lane >> 4) << 3);
    const uint32_t kb_off  = ((lane >> 3) & 1) << 4;
    const uint32_t v_row = (lane & 7) + (((lane >> 3) & 1) << 3);
    const uint32_t v_off = (lane >> 4) << 4;

    float m0 = -1e30f, m1 = -1e30f, l0 = 0.f, l1 = 0.f;
    float O[4][4];
    #pragma unroll
    for (int j = 0; j < 4; j++)
        #pragma unroll
        for (int i = 0; i < 4; i++) O[j][i] = 0.f;

    for (int kt = 0; kt < Nq; kt += 64) {
        // ---- K/V tiles: 64 x 32 fp32 each -> hi/lo bf16 ----------------------
        #pragma unroll
        for (int i = 0; i < 2; i++) {
            int idx = i * 256 + t;
            int r = idx >> 3, q = (idx & 7) << 2;
            const float* rp = &base[(size_t)(kt + r) * 768 + q];
            uint32_t h01, h23, g01, g23;
            float4 kv = *(const float4*)(rp + 256);
            split4(kv, h01, h23, g01, g23);
            uint32_t kd = kB + r * ASTRIDE + (q << 1);
            asm volatile("st.shared.v2.b32 [%0], {%1,%2};" :: "r"(kd), "r"(h01), "r"(h23));
            asm volatile("st.shared.v2.b32 [%0], {%1,%2};" :: "r"(kd + 64), "r"(g01), "r"(g23));
            float4 vv = *(const float4*)(rp + 512);
            split4(vv, h01, h23, g01, g23);
            uint32_t vd = vB + r * ASTRIDE + (q << 1);
            asm volatile("st.shared.v2.b32 [%0], {%1,%2};" :: "r"(vd), "r"(h01), "r"(h23));
            asm volatile("st.shared.v2.b32 [%0], {%1,%2};" :: "r"(vd + 64), "r"(g01), "r"(g23));
        }
        __syncthreads();

        // ---- S = Q K^T (3-term split) ----------------------------------------
        float S[8][4];
        #pragma unroll
        for (int nt = 0; nt < 8; nt++)
            #pragma unroll
            for (int i = 0; i < 4; i++) S[nt][i] = 0.f;

        #pragma unroll
        for (int ks = 0; ks < 2; ks++) {
            uint32_t ah[4], al[4];
            uint32_t ad = qB + a_row * ASTRIDE + (ks << 5) + a_off;
            LDSM4(ah, ad);
            LDSM4(al, ad + 64);
            #pragma unroll
            for (int gg = 0; gg < 4; gg++) {
                uint32_t bh4[4], bl4[4];
                uint32_t kd = kB + (gg * 16 + kb_part) * ASTRIDE + (ks << 5) + kb_off;
                LDSM4(bh4, kd);
                LDSM4(bl4, kd + 64);
                #pragma unroll
                for (int sub = 0; sub < 2; sub++) {
                    const int nt = gg * 2 + sub, rs = sub << 1;
                    MMA16816(S[nt], ah, bh4[rs], bh4[rs + 1]);
                    MMA16816(S[nt], ah, bl4[rs], bl4[rs + 1]);
                    MMA16816(S[nt], al, bh4[rs], bh4[rs + 1]);
                }
            }
        }

        // ---- online softmax in fragments -------------------------------------
        float mt0 = -1e30f, mt1 = -1e30f;
        #pragma unroll
        for (int nt = 0; nt < 8; nt++) {
            #pragma unroll
            for (int i = 0; i < 4; i++) S[nt][i] *= SCALE_ATT;
            mt0 = fmaxf(mt0, fmaxf(S[nt][0], S[nt][1]));
            mt1 = fmaxf(mt1, fmaxf(S[nt][2], S[nt][3]));
        }
        mt0 = fmaxf(mt0, __shfl_xor_sync(0xffffffffu, mt0, 1));
        mt0 = fmaxf(mt0, __shfl_xor_sync(0xffffffffu, mt0, 2));
        mt1 = fmaxf(mt1, __shfl_xor_sync(0xffffffffu, mt1, 1));
        mt1 = fmaxf(mt1, __shfl_xor_sync(0xffffffffu, mt1, 2));
        const float mn0 = fmaxf(m0, mt0), mn1 = fmaxf(m1, mt1);
        const float al0 = __expf(m0 - mn0), al1 = __expf(m1 - mn1);
        l0 *= al0; l1 *= al1;
        #pragma unroll
        for (int j = 0; j < 4; j++) {
            O[j][0] *= al0; O[j][1] *= al0; O[j][2] *= al1; O[j][3] *= al1;
        }

        uint32_t ph01[8], ph23[8], pl01[8], pl23[8];
        float rs0 = 0.f, rs1 = 0.f;
        #pragma unroll
        for (int nt = 0; nt < 8; nt++) {
            float p0 = __expf(S[nt][0] - mn0);
            float p1 = __expf(S[nt][1] - mn0);
            float p2 = __expf(S[nt][2] - mn1);
            float p3 = __expf(S[nt][3] - mn1);
            rs0 += p0 + p1; rs1 += p2 + p3;
            split2(p0, p1, ph01[nt], pl01[nt]);
            split2(p2, p3, ph23[nt], pl23[nt]);
        }
        rs0 += __shfl_xor_sync(0xffffffffu, rs0, 1);
        rs0 += __shfl_xor_sync(0xffffffffu, rs0, 2);
        rs1 += __shfl_xor_sync(0xffffffffu, rs1, 1);
        rs1 += __shfl_xor_sync(0xffffffffu, rs1, 2);
        l0 += rs0; l1 += rs1;
        m0 = mn0; m1 = mn1;

        // ---- O += P V (3-term split) ------------------------------------------
        #pragma unroll
        for (int s = 0; s < 4; s++) {
            uint32_t pah[4] = {ph01[2*s], ph23[2*s], ph01[2*s+1], ph23[2*s+1]};
            uint32_t pal[4] = {pl01[2*s], pl23[2*s], pl01[2*s+1], pl23[2*s+1]};
            #pragma unroll
            for (int hof = 0; hof < 2; hof++) {
                uint32_t vh4[4], vl4[4];
                uint32_t vd = vB + (s * 16 + v_row) * ASTRIDE + (hof << 5) + v_off;
                LDSM4_T(vh4, vd);
                LDSM4_T(vl4, vd + 64);
                #pragma unroll
                for (int sub = 0; sub < 2; sub++) {
                    const int j = hof * 2 + sub, rs = sub << 1;
                    MMA16816(O[j], pah, vh4[rs], vh4[rs + 1]);
                    MMA16816(O[j], pah, vl4[rs], vl4[rs + 1]);
                    MMA16816(O[j], pal, vh4[rs], vh4[rs + 1]);
                }
            }
        }
        __syncthreads();
    }

    // ---- epilogue --------------------------------------------------------------
    const float inv0 = 1.f / l0, inv1 = 1.f / l1;
    const int gr = lane >> 2, c2 = (lane & 3) << 1;
    const int row0 = q0 + wm16 + gr;
    float* op = out + ((size_t)(b * Nq + row0)) * Dq + h * HDq;
    #pragma unroll
    for (int j = 0; j < 4; j++) {
        const int col = j * 8 + c2;
        *(float2*)&op[col] = make_float2(O[j][0] * inv0, O[j][1] * inv0);
        *(float2*)&op[8 * (size_t)Dq + col] = make_float2(O[j][2] * inv1, O[j][3] * inv1);
    }
}

// ---------------- per-row LayerNorm -------------------------------------------
__device__ __forceinline__ float blk_sum256(float v, float* sh8)
{
    const int t = threadIdx.x;
    #pragma unroll
    for (int o = 16; o > 0; o >>= 1) v += __shfl_xor_sync(0xffffffffu, v, o);
    if ((t & 31) == 0) sh8[t >> 5] = v;
    __syncthreads();
    float r = 0.f;
    #pragma unroll
    for (int i = 0; i < 8; i++) r += sh8[i];
    __syncthreads();
    return r;
}

__global__ void ln_kernel(const float* __restrict__ in, const float* __restrict__ g,
                          const float* __restrict__ be, float* __restrict__ outp)
{
    __shared__ float sh8[8];
    const int row = blockIdx.x;
    const int t = threadIdx.x;
    const float v = in[(size_t)row * Dq + t];
    const float mu = blk_sum256(v, sh8) * (1.0f / Dq);
    const float d = v - mu;
    const float var = blk_sum256(d * d, sh8) * (1.0f / Dq);
    const float inv = rsqrtf(var + 1e-5f);
    outp[(size_t)row * Dq + t] = d * inv * g[t] + be[t];
}

// ---------------- launch ------------------------------------------------------
extern "C" void kernel_launch(void* const* d_in, const int* in_sizes, int n_in,
                              void* d_out, int out_size)
{
    const float* x      = (const float*)d_in[0];
    const float* qkv_w  = (const float*)d_in[1];
    const float* proj_w = (const float*)d_in[2];
    const float* proj_b = (const float*)d_in[3];
    const float* fc1_w  = (const float*)d_in[4];
    const float* fc1_b  = (const float*)d_in[5];
    const float* fc2_w  = (const float*)d_in[6];
    const float* fc2_b  = (const float*)d_in[7];
    const float* ln1_g  = (const float*)d_in[8];
    const float* ln1_b  = (const float*)d_in[9];
    float* out = (float*)d_out;

    float *p_qkv, *p_att, *p_proj, *p_net, *p_h1;
    cudaGetSymbolAddress((void**)&p_qkv,  g_qkv);
    cudaGetSymbolAddress((void**)&p_att,  g_att);
    cudaGetSymbolAddress((void**)&p_proj, g_proj);
    cudaGetSymbolAddress((void**)&p_net,  g_net);
    cudaGetSymbolAddress((void**)&p_h1,   g_h1);

    // 1) QKV = X @ Wqkv                     [4096,256]@[256,768]
    gemm_mma<<<dim3(3 * Dq / 64, ROWS / 128), 256>>>(
        x, qkv_w, nullptr, nullptr, p_qkv, ROWS, 3 * Dq, Dq);
    // 2) attention -> [4096,256]
    attn_mma<<<dim3(Nq / 128, Bq * Hq), 256>>>(p_qkv, p_att);
    // 3) proj + bias + residual x           [4096,256]@[256,256]
    gemm_mma<<<dim3(Dq / 64, ROWS / 128), 256>>>(
        p_att, proj_w, proj_b, x, p_proj, ROWS, Dq, Dq);
    // 4) LayerNorm -> shortcut
    ln_kernel<<<ROWS, 256>>>(p_proj, ln1_g, ln1_b, p_net);
    // 5) fc1 + bias                         [4096,256]@[256,1024]
    gemm_mma<<<dim3(DFFq / 64, ROWS / 128), 256>>>(
        p_net, fc1_w, fc1_b, nullptr, p_h1, ROWS, DFFq, Dq);
    // 6) fc2 + bias + shortcut -> d_out     [4096,1024]@[1024,256]
    gemm_mma<<<dim3(Dq / 64, ROWS / 128), 256>>>(
        p_h1, fc2_w, fc2_b, p_net, out, ROWS, Dq, DFFq);
}